// round 1
// baseline (speedup 1.0000x reference)
#include <cuda_runtime.h>
#include <math.h>

// Problem constants
// B=2, L=1024, E=1024, H=8, D=64, N_ITERS=20
#define NBH   16        // B*H
#define LSEQ  1024
#define DH    64
#define EDIM  1024
#define HD    512       // H*D
#define MROWS 2048      // B*L
#define NITERS 20

// ---------------- scratch (device globals; no runtime allocation) ----------
__device__ float g_q[NBH * LSEQ * DH];            // 4 MB  [bh][l][d]
__device__ float g_k[NBH * LSEQ * DH];            // 4 MB
__device__ float g_v[NBH * LSEQ * DH];            // 4 MB
__device__ float g_logits[NBH * LSEQ * LSEQ];     // 64 MB [bh][i][j]
__device__ float g_r[NBH * LSEQ];                 // row potentials
__device__ float g_c[NBH * LSEQ];                 // col potentials
__device__ float g_attn[MROWS * HD];              // 4 MB  [b*L + l][h*64 + d]

// ============================================================================
// QKV projection: C = x(2048x1024) @ W(1024x512) + bias, scattered to
// g_{q,k,v}[bh][l][d].  blockIdx.z selects which projection.
// 128x128x8 register-tiled fp32 GEMM, 256 threads, 8x8 per thread.
// ============================================================================
__global__ __launch_bounds__(256) void qkv_kernel(
    const float* __restrict__ x,
    const float* __restrict__ Wq, const float* __restrict__ bq,
    const float* __restrict__ Wk, const float* __restrict__ bk,
    const float* __restrict__ Wv, const float* __restrict__ bv)
{
    const float* W; const float* bias; float* out;
    if (blockIdx.z == 0)      { W = Wq; bias = bq; out = g_q; }
    else if (blockIdx.z == 1) { W = Wk; bias = bk; out = g_k; }
    else                      { W = Wv; bias = bv; out = g_v; }

    __shared__ float As[8][132];   // [k][m], padded
    __shared__ float Bs[8][132];   // [k][n], padded

    const int m0 = blockIdx.y * 128;
    const int n0 = blockIdx.x * 128;
    const int tid = threadIdx.x;
    const int tx = tid & 15, ty = tid >> 4;

    const int arow = tid >> 1;          // 0..127
    const int akq  = (tid & 1) * 4;     // 0 or 4
    const int brow = tid >> 5;          // 0..7
    const int bcol = (tid & 31) * 4;    // 0..124

    float acc[8][8] = {};

    for (int k0 = 0; k0 < EDIM; k0 += 8) {
        float4 av = *(const float4*)(x + (m0 + arow) * EDIM + k0 + akq);
        As[akq + 0][arow] = av.x; As[akq + 1][arow] = av.y;
        As[akq + 2][arow] = av.z; As[akq + 3][arow] = av.w;
        float4 wv = *(const float4*)(W + (k0 + brow) * HD + n0 + bcol);
        *(float4*)&Bs[brow][bcol] = wv;
        __syncthreads();
        #pragma unroll
        for (int kk = 0; kk < 8; kk++) {
            float a[8], b[8];
            *(float4*)(a)     = *(float4*)&As[kk][ty * 8];
            *(float4*)(a + 4) = *(float4*)&As[kk][ty * 8 + 4];
            *(float4*)(b)     = *(float4*)&Bs[kk][tx * 8];
            *(float4*)(b + 4) = *(float4*)&Bs[kk][tx * 8 + 4];
            #pragma unroll
            for (int i = 0; i < 8; i++)
                #pragma unroll
                for (int j = 0; j < 8; j++)
                    acc[i][j] += a[i] * b[j];
        }
        __syncthreads();
    }

    #pragma unroll
    for (int i = 0; i < 8; i++) {
        int m = m0 + ty * 8 + i;
        int bb = m >> 10, l = m & 1023;
        #pragma unroll
        for (int j = 0; j < 8; j++) {
            int n = n0 + tx * 8 + j;
            int h = n >> 6, d = n & 63;
            out[(((bb << 3) + h) << 16) + (l << 6) + d] = acc[i][j] + bias[n];
        }
    }
}

// ============================================================================
// logits[bh] = Q[bh] (1024x64) @ K[bh]^T (64x1024) * 0.125
// Same 128x128x8 skeleton; B tile loaded transposed from K.
// grid (8, 8, 16)
// ============================================================================
__global__ __launch_bounds__(256) void logits_kernel()
{
    __shared__ float As[8][132];
    __shared__ float Bs[8][132];

    const int bh = blockIdx.z;
    const int m0 = blockIdx.y * 128;
    const int n0 = blockIdx.x * 128;
    const int tid = threadIdx.x;
    const int tx = tid & 15, ty = tid >> 4;

    const float* Qp = g_q + bh * (LSEQ * DH);
    const float* Kp = g_k + bh * (LSEQ * DH);
    float*       Lp = g_logits + (size_t)bh * (LSEQ * LSEQ);

    const int arow = tid >> 1;
    const int akq  = (tid & 1) * 4;

    float acc[8][8] = {};

    for (int k0 = 0; k0 < DH; k0 += 8) {
        float4 av = *(const float4*)(Qp + (m0 + arow) * DH + k0 + akq);
        As[akq + 0][arow] = av.x; As[akq + 1][arow] = av.y;
        As[akq + 2][arow] = av.z; As[akq + 3][arow] = av.w;
        // B[k][n] = K[n][k]
        float4 kv = *(const float4*)(Kp + (n0 + arow) * DH + k0 + akq);
        Bs[akq + 0][arow] = kv.x; Bs[akq + 1][arow] = kv.y;
        Bs[akq + 2][arow] = kv.z; Bs[akq + 3][arow] = kv.w;
        __syncthreads();
        #pragma unroll
        for (int kk = 0; kk < 8; kk++) {
            float a[8], b[8];
            *(float4*)(a)     = *(float4*)&As[kk][ty * 8];
            *(float4*)(a + 4) = *(float4*)&As[kk][ty * 8 + 4];
            *(float4*)(b)     = *(float4*)&Bs[kk][tx * 8];
            *(float4*)(b + 4) = *(float4*)&Bs[kk][tx * 8 + 4];
            #pragma unroll
            for (int i = 0; i < 8; i++)
                #pragma unroll
                for (int j = 0; j < 8; j++)
                    acc[i][j] += a[i] * b[j];
        }
        __syncthreads();
    }

    #pragma unroll
    for (int i = 0; i < 8; i++) {
        int m = m0 + ty * 8 + i;
        #pragma unroll
        for (int j = 0; j < 8; j++) {
            int n = n0 + tx * 8 + j;
            Lp[m * LSEQ + n] = acc[i][j] * 0.125f;
        }
    }
}

// ============================================================================
// Sinkhorn potentials.  r_i = log sum_j exp(l_ij - c_j);
//                       c_j = log sum_i exp(l_ij - r_i)
// (no max-subtraction: logits ~ N(0,1), potentials O(log L); fp32-safe)
// ============================================================================
__global__ void init_c_kernel() {
    g_c[blockIdx.x * 1024 + threadIdx.x] = 0.0f;
}

__global__ __launch_bounds__(256) void row_pass()   // grid 16384, 256 thr
{
    const int row = blockIdx.x;           // bh*1024 + i
    const int bh  = row >> 10;
    const int tid = threadIdx.x;

    float4 lv = *(const float4*)(g_logits + (size_t)row * LSEQ + tid * 4);
    float4 cv = *(const float4*)(g_c + (bh << 10) + tid * 4);
    float s = __expf(lv.x - cv.x) + __expf(lv.y - cv.y)
            + __expf(lv.z - cv.z) + __expf(lv.w - cv.w);

    #pragma unroll
    for (int off = 16; off; off >>= 1)
        s += __shfl_xor_sync(0xffffffffu, s, off);

    __shared__ float ws[8];
    if ((tid & 31) == 0) ws[tid >> 5] = s;
    __syncthreads();
    if (tid == 0) {
        float tot = ws[0] + ws[1] + ws[2] + ws[3] + ws[4] + ws[5] + ws[6] + ws[7];
        g_r[row] = __logf(tot);
    }
}

__global__ void col_pass()   // grid (16, 16), block (64, 8)
{
    const int bh = blockIdx.y;
    const int j  = blockIdx.x * 64 + threadIdx.x;
    const float* Lp = g_logits + (size_t)bh * (LSEQ * LSEQ);
    const float* rp = g_r + (bh << 10);

    float s = 0.0f;
    const int i0 = threadIdx.y * 128;
    #pragma unroll 4
    for (int ii = 0; ii < 128; ii++) {
        int i = i0 + ii;
        s += __expf(Lp[i * LSEQ + j] - rp[i]);
    }

    __shared__ float part[8][64];
    part[threadIdx.y][threadIdx.x] = s;
    __syncthreads();
    if (threadIdx.y == 0) {
        float tot = 0.0f;
        #pragma unroll
        for (int y = 0; y < 8; y++) tot += part[y][threadIdx.x];
        g_c[(bh << 10) + j] = __logf(tot);
    }
}

// ============================================================================
// out[bh] = exp(logits - r_i - c_j) @ V[bh]  -> g_attn[b*L + i][h*64 + d]
// BM=128, BN=64, BK=8; 256 threads, 8x4 per thread.  grid (8, 16)
// ============================================================================
__global__ __launch_bounds__(256) void attnv_kernel()
{
    __shared__ float As[8][132];   // exp-ed attention, [k][m]
    __shared__ float Bs[8][64];    // V tile [k][n]

    const int bh = blockIdx.y;
    const int m0 = blockIdx.x * 128;
    const int tid = threadIdx.x;
    const int tx = tid & 15, ty = tid >> 4;

    const float* Lp = g_logits + (size_t)bh * (LSEQ * LSEQ);
    const float* Vp = g_v + bh * (LSEQ * DH);
    const float* cp = g_c + (bh << 10);

    const int arow = tid >> 1;
    const int akq  = (tid & 1) * 4;
    const int brow = tid >> 5;          // 0..7
    const int bcol = (tid & 31) * 2;    // 0..62

    const float r_arow = g_r[(bh << 10) + m0 + arow];

    float acc[8][4] = {};

    for (int k0 = 0; k0 < LSEQ; k0 += 8) {
        float4 lv = *(const float4*)(Lp + (m0 + arow) * LSEQ + k0 + akq);
        float4 cv = *(const float4*)(cp + k0 + akq);
        As[akq + 0][arow] = __expf(lv.x - r_arow - cv.x);
        As[akq + 1][arow] = __expf(lv.y - r_arow - cv.y);
        As[akq + 2][arow] = __expf(lv.z - r_arow - cv.z);
        As[akq + 3][arow] = __expf(lv.w - r_arow - cv.w);
        float2 vv = *(const float2*)(Vp + (k0 + brow) * DH + bcol);
        Bs[brow][bcol]     = vv.x;
        Bs[brow][bcol + 1] = vv.y;
        __syncthreads();
        #pragma unroll
        for (int kk = 0; kk < 8; kk++) {
            float a[8], b[4];
            *(float4*)(a)     = *(float4*)&As[kk][ty * 8];
            *(float4*)(a + 4) = *(float4*)&As[kk][ty * 8 + 4];
            *(float4*)(b)     = *(float4*)&Bs[kk][tx * 4];
            #pragma unroll
            for (int i = 0; i < 8; i++)
                #pragma unroll
                for (int j = 0; j < 4; j++)
                    acc[i][j] += a[i] * b[j];
        }
        __syncthreads();
    }

    const int bb = bh >> 3, h = bh & 7;
    #pragma unroll
    for (int i = 0; i < 8; i++) {
        int m = m0 + ty * 8 + i;
        #pragma unroll
        for (int j = 0; j < 4; j++) {
            int n = tx * 4 + j;
            g_attn[(bb * LSEQ + m) * HD + h * DH + n] = acc[i][j];
        }
    }
}

// ============================================================================
// Output projection: d_out = g_attn(2048x512) @ Wo(512x1024) + bo
// grid (8, 16)
// ============================================================================
__global__ __launch_bounds__(256) void out_kernel(
    const float* __restrict__ Wo, const float* __restrict__ bo,
    float* __restrict__ out)
{
    __shared__ float As[8][132];
    __shared__ float Bs[8][132];

    const int m0 = blockIdx.y * 128;
    const int n0 = blockIdx.x * 128;
    const int tid = threadIdx.x;
    const int tx = tid & 15, ty = tid >> 4;

    const int arow = tid >> 1;
    const int akq  = (tid & 1) * 4;
    const int brow = tid >> 5;
    const int bcol = (tid & 31) * 4;

    float acc[8][8] = {};

    for (int k0 = 0; k0 < HD; k0 += 8) {
        float4 av = *(const float4*)(g_attn + (m0 + arow) * HD + k0 + akq);
        As[akq + 0][arow] = av.x; As[akq + 1][arow] = av.y;
        As[akq + 2][arow] = av.z; As[akq + 3][arow] = av.w;
        float4 wv = *(const float4*)(Wo + (k0 + brow) * EDIM + n0 + bcol);
        *(float4*)&Bs[brow][bcol] = wv;
        __syncthreads();
        #pragma unroll
        for (int kk = 0; kk < 8; kk++) {
            float a[8], b[8];
            *(float4*)(a)     = *(float4*)&As[kk][ty * 8];
            *(float4*)(a + 4) = *(float4*)&As[kk][ty * 8 + 4];
            *(float4*)(b)     = *(float4*)&Bs[kk][tx * 8];
            *(float4*)(b + 4) = *(float4*)&Bs[kk][tx * 8 + 4];
            #pragma unroll
            for (int i = 0; i < 8; i++)
                #pragma unroll
                for (int j = 0; j < 8; j++)
                    acc[i][j] += a[i] * b[j];
        }
        __syncthreads();
    }

    #pragma unroll
    for (int i = 0; i < 8; i++) {
        int m = m0 + ty * 8 + i;
        #pragma unroll
        for (int j = 0; j < 8; j++) {
            int n = n0 + tx * 8 + j;
            out[m * EDIM + n] = acc[i][j] + bo[n];
        }
    }
}

// ============================================================================
extern "C" void kernel_launch(void* const* d_in, const int* in_sizes, int n_in,
                              void* d_out, int out_size)
{
    const float* x  = (const float*)d_in[0];
    const float* Wq = (const float*)d_in[1];
    const float* bq = (const float*)d_in[2];
    const float* Wk = (const float*)d_in[3];
    const float* bk = (const float*)d_in[4];
    const float* Wv = (const float*)d_in[5];
    const float* bv = (const float*)d_in[6];
    const float* Wo = (const float*)d_in[7];
    const float* bo = (const float*)d_in[8];
    float* out = (float*)d_out;

    // 1) QKV projections (3 GEMMs in one launch via blockIdx.z)
    qkv_kernel<<<dim3(4, 16, 3), 256>>>(x, Wq, bq, Wk, bk, Wv, bv);

    // 2) logits = Q K^T / sqrt(D), materialized once (64 MB, stays in L2)
    logits_kernel<<<dim3(8, 8, 16), 256>>>();

    // 3) Sinkhorn in dual-potential form: log_alpha = logits - r_i - c_j
    init_c_kernel<<<16, 1024>>>();
    for (int it = 0; it < NITERS; it++) {
        row_pass<<<NBH * LSEQ, 256>>>();
        col_pass<<<dim3(16, NBH), dim3(64, 8)>>>();
    }

    // 4) out = exp(logits - r - c) @ V, scattered to [b*L + l][h*64 + d]
    attnv_kernel<<<dim3(8, NBH), 256>>>();

    // 5) final projection + bias
    out_kernel<<<dim3(8, 16), 256>>>(Wo, bo, out);
}

// round 2
// speedup vs baseline: 1.3087x; 1.3087x over previous
#include <cuda_runtime.h>
#include <cuda_fp16.h>
#include <math.h>

// Problem constants: B=2, L=1024, E=1024, H=8, D=64, N_ITERS=20
#define NBH   16
#define LSEQ  1024
#define DH    64
#define EDIM  1024
#define HD    512
#define MROWS 2048
#define NITERS 20

// ---------------- scratch (device globals) ----------------
__device__ float  g_q[NBH * LSEQ * DH];           // 4 MB  [bh][l][d]
__device__ float  g_k[NBH * LSEQ * DH];           // 4 MB
__device__ float  g_v[NBH * LSEQ * DH];           // 4 MB
__device__ __half g_P[NBH * LSEQ * LSEQ];         // 32 MB Gibbs kernel exp(logits/8)
__device__ float  g_ur[NBH * LSEQ];               // row scalings u_i
__device__ float  g_vc[NBH * LSEQ];               // col scalings v_j
__device__ float  g_attn[MROWS * HD];             // 4 MB  [b*L+l][h*64+d]

// ============================================================================
// QKV projection: 128x128x8 register-tiled fp32 GEMM (unchanged from R1)
// ============================================================================
__global__ __launch_bounds__(256) void qkv_kernel(
    const float* __restrict__ x,
    const float* __restrict__ Wq, const float* __restrict__ bq,
    const float* __restrict__ Wk, const float* __restrict__ bk,
    const float* __restrict__ Wv, const float* __restrict__ bv)
{
    const float* W; const float* bias; float* out;
    if (blockIdx.z == 0)      { W = Wq; bias = bq; out = g_q; }
    else if (blockIdx.z == 1) { W = Wk; bias = bk; out = g_k; }
    else                      { W = Wv; bias = bv; out = g_v; }

    __shared__ float As[8][132];
    __shared__ float Bs[8][132];

    const int m0 = blockIdx.y * 128;
    const int n0 = blockIdx.x * 128;
    const int tid = threadIdx.x;
    const int tx = tid & 15, ty = tid >> 4;

    const int arow = tid >> 1;
    const int akq  = (tid & 1) * 4;
    const int brow = tid >> 5;
    const int bcol = (tid & 31) * 4;

    float acc[8][8] = {};

    for (int k0 = 0; k0 < EDIM; k0 += 8) {
        float4 av = *(const float4*)(x + (m0 + arow) * EDIM + k0 + akq);
        As[akq + 0][arow] = av.x; As[akq + 1][arow] = av.y;
        As[akq + 2][arow] = av.z; As[akq + 3][arow] = av.w;
        float4 wv = *(const float4*)(W + (k0 + brow) * HD + n0 + bcol);
        *(float4*)&Bs[brow][bcol] = wv;
        __syncthreads();
        #pragma unroll
        for (int kk = 0; kk < 8; kk++) {
            float a[8], b[8];
            *(float4*)(a)     = *(float4*)&As[kk][ty * 8];
            *(float4*)(a + 4) = *(float4*)&As[kk][ty * 8 + 4];
            *(float4*)(b)     = *(float4*)&Bs[kk][tx * 8];
            *(float4*)(b + 4) = *(float4*)&Bs[kk][tx * 8 + 4];
            #pragma unroll
            for (int i = 0; i < 8; i++)
                #pragma unroll
                for (int j = 0; j < 8; j++)
                    acc[i][j] += a[i] * b[j];
        }
        __syncthreads();
    }

    #pragma unroll
    for (int i = 0; i < 8; i++) {
        int m = m0 + ty * 8 + i;
        int bb = m >> 10, l = m & 1023;
        #pragma unroll
        for (int j = 0; j < 8; j++) {
            int n = n0 + tx * 8 + j;
            int h = n >> 6, d = n & 63;
            out[(((bb << 3) + h) << 16) + (l << 6) + d] = acc[i][j] + bias[n];
        }
    }
}

// ============================================================================
// P[bh] = exp( Q K^T / 8 )  stored as fp16.  grid (8, 8, 16)
// ============================================================================
__global__ __launch_bounds__(256) void p_kernel()
{
    __shared__ float As[8][132];
    __shared__ float Bs[8][132];

    const int bh = blockIdx.z;
    const int m0 = blockIdx.y * 128;
    const int n0 = blockIdx.x * 128;
    const int tid = threadIdx.x;
    const int tx = tid & 15, ty = tid >> 4;

    const float* Qp = g_q + bh * (LSEQ * DH);
    const float* Kp = g_k + bh * (LSEQ * DH);
    __half*      Pp = g_P + ((size_t)bh << 20);

    const int arow = tid >> 1;
    const int akq  = (tid & 1) * 4;

    float acc[8][8] = {};

    for (int k0 = 0; k0 < DH; k0 += 8) {
        float4 av = *(const float4*)(Qp + (m0 + arow) * DH + k0 + akq);
        As[akq + 0][arow] = av.x; As[akq + 1][arow] = av.y;
        As[akq + 2][arow] = av.z; As[akq + 3][arow] = av.w;
        float4 kv = *(const float4*)(Kp + (n0 + arow) * DH + k0 + akq);
        Bs[akq + 0][arow] = kv.x; Bs[akq + 1][arow] = kv.y;
        Bs[akq + 2][arow] = kv.z; Bs[akq + 3][arow] = kv.w;
        __syncthreads();
        #pragma unroll
        for (int kk = 0; kk < 8; kk++) {
            float a[8], b[8];
            *(float4*)(a)     = *(float4*)&As[kk][ty * 8];
            *(float4*)(a + 4) = *(float4*)&As[kk][ty * 8 + 4];
            *(float4*)(b)     = *(float4*)&Bs[kk][tx * 8];
            *(float4*)(b + 4) = *(float4*)&Bs[kk][tx * 8 + 4];
            #pragma unroll
            for (int i = 0; i < 8; i++)
                #pragma unroll
                for (int j = 0; j < 8; j++)
                    acc[i][j] += a[i] * b[j];
        }
        __syncthreads();
    }

    #pragma unroll
    for (int i = 0; i < 8; i++) {
        int m = m0 + ty * 8 + i;
        __half hbuf[8];
        #pragma unroll
        for (int j = 0; j < 8; j++)
            hbuf[j] = __float2half_rn(__expf(acc[i][j] * 0.125f));
        *(uint4*)(Pp + (size_t)m * LSEQ + n0 + tx * 8) = *(const uint4*)hbuf;
    }
}

// ============================================================================
// Sinkhorn, multiplicative form:
//   u_i = 1 / sum_j P_ij v_j ;  v_j = 1 / sum_i P_ij u_i
// P fp16 (32 MB, L2-resident), pure FMA sweeps — no exp/log.
// ============================================================================
__global__ void init_v_kernel() {
    g_vc[blockIdx.x * 1024 + threadIdx.x] = 1.0f;
}

// One warp per row; block = 8 rows. grid 2048, block 256.
__global__ __launch_bounds__(256) void row_pass()
{
    const int row0 = blockIdx.x * 8;
    const int bh   = row0 >> 10;
    const int tid  = threadIdx.x;

    __shared__ float vs[1024];
    #pragma unroll
    for (int t = 0; t < 4; t++)
        vs[t * 256 + tid] = g_vc[(bh << 10) + t * 256 + tid];
    __syncthreads();

    const int warp = tid >> 5, lane = tid & 31;
    const int row  = row0 + warp;
    const __half* Pr = g_P + ((size_t)row << 10);

    float s = 0.0f;
    #pragma unroll
    for (int it = 0; it < 4; it++) {
        const int base = it * 256 + lane * 8;
        uint4 pk = *(const uint4*)(Pr + base);         // 8 halves
        const __half2* ph = (const __half2*)&pk;
        float4 v0 = *(const float4*)&vs[base];
        float4 v1 = *(const float4*)&vs[base + 4];
        float2 p0 = __half22float2(ph[0]);
        float2 p1 = __half22float2(ph[1]);
        float2 p2 = __half22float2(ph[2]);
        float2 p3 = __half22float2(ph[3]);
        s += p0.x * v0.x + p0.y * v0.y + p1.x * v0.z + p1.y * v0.w
           + p2.x * v1.x + p2.y * v1.y + p3.x * v1.z + p3.y * v1.w;
    }
    #pragma unroll
    for (int off = 16; off; off >>= 1)
        s += __shfl_xor_sync(0xffffffffu, s, off);
    if (lane == 0) g_ur[row] = 1.0f / s;
}

// 128 cols per block (half2 per thread), 8 row-strips. grid (8,16), block (64,8).
__global__ __launch_bounds__(512) void col_pass()
{
    const int bh = blockIdx.y;
    const int j0 = blockIdx.x * 128;
    const int tx = threadIdx.x;   // 0..63
    const int ty = threadIdx.y;   // 0..7
    const int tid = ty * 64 + tx;

    __shared__ float us[1024];
    us[tid]       = g_ur[(bh << 10) + tid];
    us[512 + tid] = g_ur[(bh << 10) + 512 + tid];
    __syncthreads();

    const __half* Pp = g_P + ((size_t)bh << 20) + j0 + tx * 2;
    float sx = 0.0f, sy = 0.0f;
    const int i0 = ty * 128;
    #pragma unroll 4
    for (int ii = 0; ii < 128; ii++) {
        const int i = i0 + ii;
        __half2 p = *(const __half2*)(Pp + ((size_t)i << 10));
        float2 pf = __half22float2(p);
        const float u = us[i];
        sx += pf.x * u;
        sy += pf.y * u;
    }

    __shared__ float part[8][128];
    part[ty][tx * 2]     = sx;
    part[ty][tx * 2 + 1] = sy;
    __syncthreads();
    if (tid < 128) {
        float tot = 0.0f;
        #pragma unroll
        for (int y = 0; y < 8; y++) tot += part[y][tid];
        g_vc[(bh << 10) + j0 + tid] = 1.0f / tot;
    }
}

// ============================================================================
// out[bh] = (P .* u_i .* v_j) @ V[bh] -> g_attn.  grid (8,16), 256 thr.
// ============================================================================
__global__ __launch_bounds__(256) void attnv_kernel()
{
    __shared__ float As[8][132];
    __shared__ float Bs[8][64];

    const int bh = blockIdx.y;
    const int m0 = blockIdx.x * 128;
    const int tid = threadIdx.x;
    const int tx = tid & 15, ty = tid >> 4;

    const __half* Pp = g_P + ((size_t)bh << 20);
    const float*  Vp = g_v + bh * (LSEQ * DH);
    const float*  vp = g_vc + (bh << 10);

    const int arow = tid >> 1;
    const int akq  = (tid & 1) * 4;
    const int brow = tid >> 5;
    const int bcol = (tid & 31) * 2;

    const float u_arow = g_ur[(bh << 10) + m0 + arow];

    float acc[8][4] = {};

    for (int k0 = 0; k0 < LSEQ; k0 += 8) {
        uint2 pk = *(const uint2*)(Pp + (size_t)(m0 + arow) * LSEQ + k0 + akq);
        const __half2* ph = (const __half2*)&pk;
        float2 a01 = __half22float2(ph[0]);
        float2 a23 = __half22float2(ph[1]);
        float4 vv = *(const float4*)(vp + k0 + akq);
        As[akq + 0][arow] = a01.x * u_arow * vv.x;
        As[akq + 1][arow] = a01.y * u_arow * vv.y;
        As[akq + 2][arow] = a23.x * u_arow * vv.z;
        As[akq + 3][arow] = a23.y * u_arow * vv.w;
        float2 vv2 = *(const float2*)(Vp + (k0 + brow) * DH + bcol);
        Bs[brow][bcol]     = vv2.x;
        Bs[brow][bcol + 1] = vv2.y;
        __syncthreads();
        #pragma unroll
        for (int kk = 0; kk < 8; kk++) {
            float a[8], b[4];
            *(float4*)(a)     = *(float4*)&As[kk][ty * 8];
            *(float4*)(a + 4) = *(float4*)&As[kk][ty * 8 + 4];
            *(float4*)(b)     = *(float4*)&Bs[kk][tx * 4];
            #pragma unroll
            for (int i = 0; i < 8; i++)
                #pragma unroll
                for (int j = 0; j < 4; j++)
                    acc[i][j] += a[i] * b[j];
        }
        __syncthreads();
    }

    const int bb = bh >> 3, h = bh & 7;
    #pragma unroll
    for (int i = 0; i < 8; i++) {
        int m = m0 + ty * 8 + i;
        #pragma unroll
        for (int j = 0; j < 4; j++) {
            int n = tx * 4 + j;
            g_attn[(bb * LSEQ + m) * HD + h * DH + n] = acc[i][j];
        }
    }
}

// ============================================================================
// Output projection: d_out = g_attn(2048x512) @ Wo(512x1024) + bo. grid (8,16)
// ============================================================================
__global__ __launch_bounds__(256) void out_kernel(
    const float* __restrict__ Wo, const float* __restrict__ bo,
    float* __restrict__ out)
{
    __shared__ float As[8][132];
    __shared__ float Bs[8][132];

    const int m0 = blockIdx.y * 128;
    const int n0 = blockIdx.x * 128;
    const int tid = threadIdx.x;
    const int tx = tid & 15, ty = tid >> 4;

    const int arow = tid >> 1;
    const int akq  = (tid & 1) * 4;
    const int brow = tid >> 5;
    const int bcol = (tid & 31) * 4;

    float acc[8][8] = {};

    for (int k0 = 0; k0 < HD; k0 += 8) {
        float4 av = *(const float4*)(g_attn + (m0 + arow) * HD + k0 + akq);
        As[akq + 0][arow] = av.x; As[akq + 1][arow] = av.y;
        As[akq + 2][arow] = av.z; As[akq + 3][arow] = av.w;
        float4 wv = *(const float4*)(Wo + (k0 + brow) * EDIM + n0 + bcol);
        *(float4*)&Bs[brow][bcol] = wv;
        __syncthreads();
        #pragma unroll
        for (int kk = 0; kk < 8; kk++) {
            float a[8], b[8];
            *(float4*)(a)     = *(float4*)&As[kk][ty * 8];
            *(float4*)(a + 4) = *(float4*)&As[kk][ty * 8 + 4];
            *(float4*)(b)     = *(float4*)&Bs[kk][tx * 8];
            *(float4*)(b + 4) = *(float4*)&Bs[kk][tx * 8 + 4];
            #pragma unroll
            for (int i = 0; i < 8; i++)
                #pragma unroll
                for (int j = 0; j < 8; j++)
                    acc[i][j] += a[i] * b[j];
        }
        __syncthreads();
    }

    #pragma unroll
    for (int i = 0; i < 8; i++) {
        int m = m0 + ty * 8 + i;
        #pragma unroll
        for (int j = 0; j < 8; j++) {
            int n = n0 + tx * 8 + j;
            out[m * EDIM + n] = acc[i][j] + bo[n];
        }
    }
}

// ============================================================================
extern "C" void kernel_launch(void* const* d_in, const int* in_sizes, int n_in,
                              void* d_out, int out_size)
{
    const float* x  = (const float*)d_in[0];
    const float* Wq = (const float*)d_in[1];
    const float* bq = (const float*)d_in[2];
    const float* Wk = (const float*)d_in[3];
    const float* bk = (const float*)d_in[4];
    const float* Wv = (const float*)d_in[5];
    const float* bv = (const float*)d_in[6];
    const float* Wo = (const float*)d_in[7];
    const float* bo = (const float*)d_in[8];
    float* out = (float*)d_out;

    qkv_kernel<<<dim3(4, 16, 3), 256>>>(x, Wq, bq, Wk, bk, Wv, bv);
    p_kernel<<<dim3(8, 8, 16), 256>>>();

    init_v_kernel<<<16, 1024>>>();
    for (int it = 0; it < NITERS; it++) {
        row_pass<<<MROWS * 8 / 8, 256>>>();       // 2048 blocks
        col_pass<<<dim3(8, NBH), dim3(64, 8)>>>();
    }

    attnv_kernel<<<dim3(8, NBH), 256>>>();
    out_kernel<<<dim3(8, 16), 256>>>(Wo, bo, out);
}